// round 7
// baseline (speedup 1.0000x reference)
#include <cuda_runtime.h>
#include <cstdint>

// Inv1x1MM_SVD, C=16, 65536 positions.
// ROW-SLAB layout, 4 lanes per position: lane (pos, r) holds rows 4r..4r+3 of
// the 16x16 working matrix, all 16 columns, packed f32x2 column pairs.
// MGS step k: column k is lane-local; dots reduced over the 4-lane group with
// a 2-stage butterfly. Norm p[k] comes fresh from the same dot pass.
// rs of QR(V) is folded into w on the fly to cut peak register pressure.

constexpr int NPOS = 8 * 8192;

#define FMA2(d, a, b, c) asm("fma.rn.f32x2 %0, %1, %2, %3;" : "=l"(d) : "l"(a), "l"(b), "l"(c))
#define MUL2(d, a, b)    asm("mul.rn.f32x2 %0, %1, %2;"     : "=l"(d) : "l"(a), "l"(b))
#define ADD2(d, a, b)    asm("add.rn.f32x2 %0, %1, %2;"     : "=l"(d) : "l"(a), "l"(b))
#define PACK2(d, lo, hi) asm("mov.b64 %0, {%1, %2};"        : "=l"(d) : "f"(lo), "f"(hi))
#define UNPACK2(lo, hi, d) asm("mov.b64 {%0, %1}, %2;" : "=f"(lo), "=f"(hi) : "l"(d))

__device__ __forceinline__ uint64_t shx(uint64_t v, int m) {
    uint32_t lo, hi;
    asm("mov.b64 {%0, %1}, %2;" : "=r"(lo), "=r"(hi) : "l"(v));
    lo = __shfl_xor_sync(0xffffffffu, lo, m);
    hi = __shfl_xor_sync(0xffffffffu, hi, m);
    uint64_t r;
    asm("mov.b64 %0, {%1, %2};" : "=l"(r) : "r"(lo), "r"(hi));
    return r;
}

// MGS over 16 columns, rows spread over a 4-lane group.
// SCALEW=false: store 1/||b_j|| into rs[16].
// SCALEW=true : multiply w[j] by 1/||b_j|| as each column finishes.
template <bool SCALEW>
__device__ __forceinline__ void mgs4(uint64_t (&A)[4][8], float* rs, uint64_t* w) {
    #pragma unroll
    for (int k = 0; k < 15; k++) {
        const int c0 = k >> 1;        // pair containing column k
        const int cu = (k + 1) >> 1;  // first pair updated

        // column k is lane-local
        uint64_t ak[4];
        #pragma unroll
        for (int i = 0; i < 4; i++) {
            float lo, hi;
            UNPACK2(lo, hi, A[i][c0]);
            const float x = (k & 1) ? hi : lo;
            PACK2(ak[i], x, x);
        }

        // dots p_j = <c_k, c_j> for all pairs >= c0, reduced over the 4 lanes
        uint64_t pp[8];
        #pragma unroll
        for (int c = 0; c < 8; c++) {
            if (c < c0) continue;
            MUL2(pp[c], ak[0], A[0][c]);
            FMA2(pp[c], ak[1], A[1][c], pp[c]);
            FMA2(pp[c], ak[2], A[2][c], pp[c]);
            FMA2(pp[c], ak[3], A[3][c], pp[c]);
            uint64_t o = shx(pp[c], 1);
            ADD2(pp[c], pp[c], o);
            o = shx(pp[c], 2);
            ADD2(pp[c], pp[c], o);
        }

        // fresh norm ||c_k||^2 = p_k
        float plo, phi;
        UNPACK2(plo, phi, pp[c0]);
        const float pk = (k & 1) ? phi : plo;
        const float r  = rsqrtf(fmaxf(pk, 1e-30f));
        if (SCALEW) {
            float wl, wh;
            UNPACK2(wl, wh, w[c0]);
            if (k & 1) wh *= r; else wl *= r;
            PACK2(w[c0], wl, wh);
        } else {
            rs[k] = r;
        }
        const float ninv = -(r * r);   // -1/||c_k||^2
        uint64_t n2;
        PACK2(n2, ninv, ninv);

        // c_j -= (p_j / ||c_k||^2) c_k   for j > k
        #pragma unroll
        for (int c = 0; c < 8; c++) {
            if (c < cu) continue;
            uint64_t s;
            MUL2(s, pp[c], n2);
            if (!(k & 1) && c == cu) {   // pair contains j == k: mask its lo half
                float sl, sh;
                UNPACK2(sl, sh, s);
                PACK2(s, 0.0f, sh);
            }
            FMA2(A[0][c], s, ak[0], A[0][c]);
            FMA2(A[1][c], s, ak[1], A[1][c]);
            FMA2(A[2][c], s, ak[2], A[2][c]);
            FMA2(A[3][c], s, ak[3], A[3][c]);
        }
    }
    // norm of column 15
    float n15 = 0.0f;
    #pragma unroll
    for (int i = 0; i < 4; i++) {
        float lo, hi;
        UNPACK2(lo, hi, A[i][7]);
        n15 = fmaf(hi, hi, n15);
    }
    n15 += __shfl_xor_sync(0xffffffffu, n15, 1);
    n15 += __shfl_xor_sync(0xffffffffu, n15, 2);
    const float r = rsqrtf(fmaxf(n15, 1e-30f));
    if (SCALEW) {
        float wl, wh;
        UNPACK2(wl, wh, w[7]);
        wh *= r;
        PACK2(w[7], wl, wh);
    } else {
        rs[15] = r;
    }
}

__device__ __forceinline__ void load_mat(uint64_t (&A)[4][8], const float4* f4, int rbase) {
    #pragma unroll
    for (int i = 0; i < 4; i++) {
        const float4 q0 = __ldg(&f4[rbase + 4 * i + 0]);
        const float4 q1 = __ldg(&f4[rbase + 4 * i + 1]);
        const float4 q2 = __ldg(&f4[rbase + 4 * i + 2]);
        const float4 q3 = __ldg(&f4[rbase + 4 * i + 3]);
        PACK2(A[i][0], q0.x, q0.y); PACK2(A[i][1], q0.z, q0.w);
        PACK2(A[i][2], q1.x, q1.y); PACK2(A[i][3], q1.z, q1.w);
        PACK2(A[i][4], q2.x, q2.y); PACK2(A[i][5], q2.z, q2.w);
        PACK2(A[i][6], q3.x, q3.y); PACK2(A[i][7], q3.z, q3.w);
    }
}

__global__ void __launch_bounds__(128)
inv1x1mm_svd_kernel(const float* __restrict__ data,
                    const float* __restrict__ paras,
                    float* __restrict__ out) {
    const int tid = threadIdx.x;
    const int r   = tid & 3;                        // row-slab index (rows 4r..4r+3)
    const int pos = blockIdx.x * 32 + (tid >> 2);   // 32 positions per block

    const float4* f4 = (const float4*)(paras + (size_t)pos * 528);

    uint64_t A[4][8];
    float rs0[16];

    // ===== QR of U =====  (U rows: float4 index 4 + 4*g, g = 4r+i)
    load_mat(A, f4, 4 + 16 * r);
    mgs4<false>(A, rs0, nullptr);

    // v_j = <data, b0_j> reduced over the 4-lane group (all lanes get all 16)
    const float4 dv = __ldg((const float4*)(data + pos * 16 + r * 4));
    uint64_t dd[4];
    PACK2(dd[0], dv.x, dv.x);
    PACK2(dd[1], dv.y, dv.y);
    PACK2(dd[2], dv.z, dv.z);
    PACK2(dd[3], dv.w, dv.w);

    uint64_t w[8];
    #pragma unroll
    for (int c = 0; c < 8; c++) {
        MUL2(w[c], dd[0], A[0][c]);
        FMA2(w[c], dd[1], A[1][c], w[c]);
        FMA2(w[c], dd[2], A[2][c], w[c]);
        FMA2(w[c], dd[3], A[3][c], w[c]);
        uint64_t o = shx(w[c], 1);
        ADD2(w[c], w[c], o);
        o = shx(w[c], 2);
        ADD2(w[c], w[c], o);
    }

    // w_j = v_j * rs0_j * exp(ls_j)
    {
        const float4 l0 = __ldg(&f4[0]);
        const float4 l1 = __ldg(&f4[1]);
        const float4 l2 = __ldg(&f4[2]);
        const float4 l3 = __ldg(&f4[3]);
        const float e[16] = {
            __expf(l0.x), __expf(l0.y), __expf(l0.z), __expf(l0.w),
            __expf(l1.x), __expf(l1.y), __expf(l1.z), __expf(l1.w),
            __expf(l2.x), __expf(l2.y), __expf(l2.z), __expf(l2.w),
            __expf(l3.x), __expf(l3.y), __expf(l3.z), __expf(l3.w)};
        #pragma unroll
        for (int c = 0; c < 8; c++) {
            uint64_t m;
            PACK2(m, e[2 * c] * rs0[2 * c], e[2 * c + 1] * rs0[2 * c + 1]);
            MUL2(w[c], w[c], m);
        }
    }

    // ===== QR of V =====  (folds 1/||b1_j|| into w on the fly)
    load_mat(A, f4, 68 + 16 * r);
    mgs4<true>(A, nullptr, w);

    // res_d = sum_j w_j * b1[d][j]   (d = my 4 local rows)
    float o[4];
    #pragma unroll
    for (int i = 0; i < 4; i++) {
        uint64_t acc;
        MUL2(acc, w[0], A[i][0]);
        #pragma unroll
        for (int c = 1; c < 8; c++) FMA2(acc, w[c], A[i][c], acc);
        float lo, hi;
        UNPACK2(lo, hi, acc);
        o[i] = lo + hi;
    }

    *(float4*)(out + pos * 16 + r * 4) = make_float4(o[0], o[1], o[2], o[3]);
}

extern "C" void kernel_launch(void* const* d_in, const int* in_sizes, int n_in,
                              void* d_out, int out_size) {
    const float* data  = (const float*)d_in[0];
    const float* paras = (const float*)d_in[1];
    if (n_in >= 2 && in_sizes[0] > in_sizes[1]) {  // defensive ordering by size
        data  = (const float*)d_in[1];
        paras = (const float*)d_in[0];
    }
    inv1x1mm_svd_kernel<<<NPOS / 32, 128>>>(data, paras, (float*)d_out);
}

// round 8
// speedup vs baseline: 1.1093x; 1.1093x over previous
#include <cuda_runtime.h>
#include <cstdint>

// Inv1x1MM_SVD, C=16, 65536 positions.
// ROW-SLAB layout, 2 lanes per position (R6 base): lane (pos, half) holds rows
// half*8..half*8+7 of the 16x16 working matrix, packed f32x2 column pairs.
// MGS step k: column k lane-local; dots via dual-accumulator trees reduced
// with ONE shfl level. U's inverse norms go to smem (frees 16 regs); V's are
// folded into w on the fly (frees 16 more). rcp.approx off-path of rsqrt.

constexpr int NPOS = 8 * 8192;

#define FMA2(d, a, b, c) asm("fma.rn.f32x2 %0, %1, %2, %3;" : "=l"(d) : "l"(a), "l"(b), "l"(c))
#define MUL2(d, a, b)    asm("mul.rn.f32x2 %0, %1, %2;"     : "=l"(d) : "l"(a), "l"(b))
#define ADD2(d, a, b)    asm("add.rn.f32x2 %0, %1, %2;"     : "=l"(d) : "l"(a), "l"(b))
#define PACK2(d, lo, hi) asm("mov.b64 %0, {%1, %2};"        : "=l"(d) : "f"(lo), "f"(hi))
#define UNPACK2(lo, hi, d) asm("mov.b64 {%0, %1}, %2;" : "=f"(lo), "=f"(hi) : "l"(d))

__device__ __forceinline__ uint64_t shx1(uint64_t v) {
    uint32_t lo, hi;
    asm("mov.b64 {%0, %1}, %2;" : "=r"(lo), "=r"(hi) : "l"(v));
    lo = __shfl_xor_sync(0xffffffffu, lo, 1);
    hi = __shfl_xor_sync(0xffffffffu, hi, 1);
    uint64_t r;
    asm("mov.b64 %0, {%1, %2};" : "=l"(r) : "r"(lo), "r"(hi));
    return r;
}
__device__ __forceinline__ float frcp(float x) {
    float r;
    asm("rcp.approx.f32 %0, %1;" : "=f"(r) : "f"(x));
    return r;
}

// MGS over 16 columns, rows split across a lane pair.
// SCALEW=false: write 1/||b_k|| to rs_sm[k] (writer lane only).
// SCALEW=true : fold 1/||b_k|| into w element k as columns finish.
template <bool SCALEW>
__device__ __forceinline__ void mgs2(uint64_t (&A)[8][8], uint64_t* w,
                                     float* rs_sm, bool writer) {
    #pragma unroll
    for (int k = 0; k < 15; k++) {
        const int c0 = k >> 1;        // pair containing column k
        const int cu = (k + 1) >> 1;  // first pair updated

        // column k is lane-local: duplicate into both halves
        uint64_t ak[8];
        #pragma unroll
        for (int i = 0; i < 8; i++) {
            float lo, hi;
            UNPACK2(lo, hi, A[i][c0]);
            const float x = (k & 1) ? hi : lo;
            PACK2(ak[i], x, x);
        }

        // dots p_j = <c_k, c_j>, dual-accumulator, one shfl level
        uint64_t pp[8];
        #pragma unroll
        for (int c = c0; c < 8; c++) {
            uint64_t s0, s1;
            MUL2(s0, ak[0], A[0][c]);
            MUL2(s1, ak[4], A[4][c]);
            FMA2(s0, ak[1], A[1][c], s0);
            FMA2(s1, ak[5], A[5][c], s1);
            FMA2(s0, ak[2], A[2][c], s0);
            FMA2(s1, ak[6], A[6][c], s1);
            FMA2(s0, ak[3], A[3][c], s0);
            FMA2(s1, ak[7], A[7][c], s1);
            ADD2(s0, s0, s1);
            const uint64_t o = shx1(s0);
            ADD2(pp[c], s0, o);
        }

        // fresh norm ||c_k||^2 = p_k
        float plo, phi;
        UNPACK2(plo, phi, pp[c0]);
        const float pk = fmaxf((k & 1) ? phi : plo, 1e-30f);
        const float ninv = -frcp(pk);          // update path (MUFU.RCP)
        const float r = rsqrtf(pk);            // scaling path (parallel MUFU.RSQ)
        if (SCALEW) {
            float wl, wh;
            UNPACK2(wl, wh, w[c0]);
            if (k & 1) wh *= r; else wl *= r;
            PACK2(w[c0], wl, wh);
        } else if (writer) {
            rs_sm[k] = r;
        }
        uint64_t n2;
        PACK2(n2, ninv, ninv);

        // c_j -= (p_j / ||c_k||^2) c_k  for j > k
        #pragma unroll
        for (int c = cu; c < 8; c++) {
            uint64_t s;
            MUL2(s, pp[c], n2);
            if (!(k & 1) && c == cu) {         // mask lo half (j == k)
                float sl, sh;
                UNPACK2(sl, sh, s);
                PACK2(s, 0.0f, sh);
            }
            #pragma unroll
            for (int i = 0; i < 8; i++) FMA2(A[i][c], s, ak[i], A[i][c]);
        }
    }
    // column 15 norm
    float n15 = 0.0f;
    #pragma unroll
    for (int i = 0; i < 8; i++) {
        float lo, hi;
        UNPACK2(lo, hi, A[i][7]);
        n15 = fmaf(hi, hi, n15);
    }
    n15 += __shfl_xor_sync(0xffffffffu, n15, 1);
    const float r = rsqrtf(fmaxf(n15, 1e-30f));
    if (SCALEW) {
        float wl, wh;
        UNPACK2(wl, wh, w[7]);
        wh *= r;
        PACK2(w[7], wl, wh);
    } else if (writer) {
        rs_sm[15] = r;
    }
}

__device__ __forceinline__ void load_mat(uint64_t (&A)[8][8], const float4* f4, int rbase) {
    #pragma unroll
    for (int i = 0; i < 8; i++) {
        const float4 q0 = __ldg(&f4[rbase + 4 * i + 0]);
        const float4 q1 = __ldg(&f4[rbase + 4 * i + 1]);
        const float4 q2 = __ldg(&f4[rbase + 4 * i + 2]);
        const float4 q3 = __ldg(&f4[rbase + 4 * i + 3]);
        PACK2(A[i][0], q0.x, q0.y); PACK2(A[i][1], q0.z, q0.w);
        PACK2(A[i][2], q1.x, q1.y); PACK2(A[i][3], q1.z, q1.w);
        PACK2(A[i][4], q2.x, q2.y); PACK2(A[i][5], q2.z, q2.w);
        PACK2(A[i][6], q3.x, q3.y); PACK2(A[i][7], q3.z, q3.w);
    }
}

__global__ void __launch_bounds__(64)
inv1x1mm_svd_kernel(const float* __restrict__ data,
                    const float* __restrict__ paras,
                    float* __restrict__ out) {
    __shared__ float rs_sm[32][17];            // stride 17: conflict-free

    const int tid  = threadIdx.x;
    const int half = tid & 1;
    const int p    = tid >> 1;                 // position within block (0..31)
    const int pos  = blockIdx.x * 32 + p;

    const float4* f4 = (const float4*)(paras + (size_t)pos * 528);
    const int rbase_u = 4 + half * 32;
    const int rbase_v = 68 + half * 32;

    // L2 prefetch: my V half (512 B), data line, ls line
    {
        const char* vp = (const char*)(f4 + rbase_v);
        #pragma unroll
        for (int i = 0; i < 4; i++)
            asm volatile("prefetch.global.L2 [%0];" :: "l"(vp + i * 128));
        if (half == 0) {
            asm volatile("prefetch.global.L2 [%0];" :: "l"((const char*)(data + pos * 16)));
            asm volatile("prefetch.global.L2 [%0];" :: "l"((const char*)f4));
        }
    }

    uint64_t A[8][8];

    // ===== QR of U =====
    load_mat(A, f4, rbase_u);
    mgs2<false>(A, nullptr, rs_sm[p], half == 0);

    // local partial dots v_j (uses U's Q before A is overwritten)
    const float4 d0 = __ldg((const float4*)(data + pos * 16 + half * 8));
    const float4 d1 = __ldg((const float4*)(data + pos * 16 + half * 8 + 4));
    uint64_t dd[8];
    PACK2(dd[0], d0.x, d0.x); PACK2(dd[1], d0.y, d0.y);
    PACK2(dd[2], d0.z, d0.z); PACK2(dd[3], d0.w, d0.w);
    PACK2(dd[4], d1.x, d1.x); PACK2(dd[5], d1.y, d1.y);
    PACK2(dd[6], d1.z, d1.z); PACK2(dd[7], d1.w, d1.w);

    uint64_t w[8];
    #pragma unroll
    for (int c = 0; c < 8; c++) {
        uint64_t s0, s1;
        MUL2(s0, dd[0], A[0][c]);
        MUL2(s1, dd[4], A[4][c]);
        FMA2(s0, dd[1], A[1][c], s0);
        FMA2(s1, dd[5], A[5][c], s1);
        FMA2(s0, dd[2], A[2][c], s0);
        FMA2(s1, dd[6], A[6][c], s1);
        FMA2(s0, dd[3], A[3][c], s0);
        FMA2(s1, dd[7], A[7][c], s1);
        ADD2(w[c], s0, s1);
    }

    // issue V loads now (overwrites A); following work hides the latency
    load_mat(A, f4, rbase_v);

    const float4 l0 = __ldg(&f4[0]);
    const float4 l1 = __ldg(&f4[1]);
    const float4 l2 = __ldg(&f4[2]);
    const float4 l3 = __ldg(&f4[3]);
    const float e[16] = {
        __expf(l0.x), __expf(l0.y), __expf(l0.z), __expf(l0.w),
        __expf(l1.x), __expf(l1.y), __expf(l1.z), __expf(l1.w),
        __expf(l2.x), __expf(l2.y), __expf(l2.z), __expf(l2.w),
        __expf(l3.x), __expf(l3.y), __expf(l3.z), __expf(l3.w)};

    __syncwarp();   // rs_sm writes (partner lane) -> reads
    #pragma unroll
    for (int c = 0; c < 8; c++) {
        const uint64_t o = shx1(w[c]);
        ADD2(w[c], w[c], o);
        uint64_t m;
        PACK2(m, e[2 * c] * rs_sm[p][2 * c], e[2 * c + 1] * rs_sm[p][2 * c + 1]);
        MUL2(w[c], w[c], m);
    }

    // ===== QR of V ===== (folds 1/||b1_j|| into w)
    mgs2<true>(A, w, nullptr, false);

    // res_d = sum_j w_j * b1[d][j]  (d = my 8 local rows)
    float o[8];
    #pragma unroll
    for (int i = 0; i < 8; i++) {
        uint64_t s0, s1;
        MUL2(s0, w[0], A[i][0]);
        MUL2(s1, w[4], A[i][4]);
        FMA2(s0, w[1], A[i][1], s0);
        FMA2(s1, w[5], A[i][5], s1);
        FMA2(s0, w[2], A[i][2], s0);
        FMA2(s1, w[6], A[i][6], s1);
        FMA2(s0, w[3], A[i][3], s0);
        FMA2(s1, w[7], A[i][7], s1);
        ADD2(s0, s0, s1);
        float lo, hi;
        UNPACK2(lo, hi, s0);
        o[i] = lo + hi;
    }

    float4* o4 = (float4*)(out + pos * 16 + half * 8);
    o4[0] = make_float4(o[0], o[1], o[2], o[3]);
    o4[1] = make_float4(o[4], o[5], o[6], o[7]);
}

extern "C" void kernel_launch(void* const* d_in, const int* in_sizes, int n_in,
                              void* d_out, int out_size) {
    const float* data  = (const float*)d_in[0];
    const float* paras = (const float*)d_in[1];
    if (n_in >= 2 && in_sizes[0] > in_sizes[1]) {  // defensive ordering by size
        data  = (const float*)d_in[1];
        paras = (const float*)d_in[0];
    }
    inv1x1mm_svd_kernel<<<NPOS / 32, 64>>>(data, paras, (float*)d_out);
}